// round 6
// baseline (speedup 1.0000x reference)
#include <cuda_runtime.h>
#include <cstdint>
#include <math.h>

// ---------------- problem constants ----------------
#define NA    100000
#define NBD   200000
#define NB    100000
#define NANG  400000
#define NG    2048
#define DIM   128
#define HID   256
#define NCB   20
#define NCA   32
#define GAMMA 10.0f
#define LN_EPS 1e-5f

// NO __device__ globals: all scratch lives inside d_out.
// d_out: [node region: NA*DIM][edge region: NBD*DIM]
// Phase E: node = agg_b; edge rows [0,NB) = bond_embed; edge rows [NB,..) = esum (NB*36).
// Phase N: node = agg_a then node output in place.

// ---------------- helpers ----------------
__device__ __forceinline__ void red_add_v4(float* addr, float4 v) {
    asm volatile("red.global.add.v4.f32 [%0], {%1, %2, %3, %4};"
                 :: "l"(addr), "f"(v.x), "f"(v.y), "f"(v.z), "f"(v.w)
                 : "memory");
}
__device__ __forceinline__ void red_add_f32(float* addr, float v) {
    asm volatile("red.global.add.f32 [%0], %1;" :: "l"(addr), "f"(v) : "memory");
}

__device__ __forceinline__ float warp_sum(float v) {
    #pragma unroll
    for (int o = 16; o > 0; o >>= 1) v += __shfl_xor_sync(0xFFFFFFFFu, v, o);
    return v;
}

__device__ __forceinline__ unsigned f2tf32(float x) {
    unsigned r;
    asm("cvt.rna.tf32.f32 %0, %1;" : "=r"(r) : "f"(x));
    return r;
}

// D += A(16x8,row) * B(8x8,col)   tf32, fp32 accum
__device__ __forceinline__ void mma8(float& d0, float& d1, float& d2, float& d3,
                                     unsigned a0, unsigned a1, unsigned a2, unsigned a3,
                                     unsigned b0, unsigned b1) {
    asm volatile("mma.sync.aligned.m16n8k8.row.col.f32.tf32.tf32.f32 "
                 "{%0,%1,%2,%3}, {%4,%5,%6,%7}, {%8,%9}, {%0,%1,%2,%3};"
                 : "+f"(d0), "+f"(d1), "+f"(d2), "+f"(d3)
                 : "r"(a0), "r"(a1), "r"(a2), "r"(a3), "r"(b0), "r"(b1));
}

// segment length of sorted gid around index u (gid[u]==g)
__device__ __forceinline__ float warp_seg_count(const int* __restrict__ gid,
                                                int M, int u, int g, int lane) {
    int r = u + 1;
    for (;;) {
        int i = r + lane;
        int v = (i < M) ? gid[i] : (g ^ 1);
        unsigned m = __ballot_sync(0xFFFFFFFFu, v != g);
        if (m) { r += __ffs(m) - 1; break; }
        r += 32;
    }
    int l = u - 1;
    for (;;) {
        int i = l - lane;
        int v = (i >= 0) ? gid[i] : (g ^ 1);
        unsigned m = __ballot_sync(0xFFFFFFFFu, v != g);
        if (m) { l -= __ffs(m) - 1; break; }
        l -= 32;
    }
    return (float)(r - l - 1);
}

// ---------------- zero a float4 range ----------------
__global__ void k_zero(float4* __restrict__ p, int n4) {
    int stride = gridDim.x * blockDim.x;
    float4 z = make_float4(0.f, 0.f, 0.f, 0.f);
    for (int i = blockIdx.x * blockDim.x + threadIdx.x; i < n4; i += stride) p[i] = z;
}

// ---------------- block A scatter: agg[dst] += nf[src] + ef[e] ----------------
__global__ void k_scatter_a(const float* __restrict__ nf, const float* __restrict__ ef,
                            const int* __restrict__ src, const int* __restrict__ dst,
                            float* __restrict__ agg) {
    int w = (blockIdx.x * blockDim.x + threadIdx.x) >> 5;
    int lane = threadIdx.x & 31;
    if (w >= NBD) return;
    int s = __ldg(&src[w]);
    int d = __ldg(&dst[w]);
    float4 a = reinterpret_cast<const float4*>(nf + (size_t)s * DIM)[lane];
    float4 b = reinterpret_cast<const float4*>(ef + (size_t)w * DIM)[lane];
    float4 v = make_float4(a.x + b.x, a.y + b.y, a.z + b.z, a.w + b.w);
    red_add_v4(agg + (size_t)d * DIM + lane * 4, v);
}

// ---------------- bond embedding -> bond_embed[u] ----------------
__global__ void k_bond_embed(const float* __restrict__ bond_float,
                             const int* __restrict__ bond_cat,
                             const float* __restrict__ bemb,
                             const float* __restrict__ rbfW,
                             const float* __restrict__ rbfb,
                             float* __restrict__ bond_embed) {
    int u = (blockIdx.x * blockDim.x + threadIdx.x) >> 5;
    int lane = threadIdx.x & 31;
    if (u >= NB) return;
    int e = 2 * u;
    float x = __ldg(&bond_float[e]);
    float ev = 0.f;
    if (lane < NCB) {
        float dlt = x - 0.1f * (float)lane;
        ev = __expf(-GAMMA * dlt * dlt);
    }
    int c0 = __ldg(&bond_cat[(size_t)e * 3 + 0]);
    int c1 = __ldg(&bond_cat[(size_t)e * 3 + 1]);
    int c2 = __ldg(&bond_cat[(size_t)e * 3 + 2]);

    float4 acc = reinterpret_cast<const float4*>(rbfb)[lane];
    float4 t;
    t = reinterpret_cast<const float4*>(bemb + (size_t)(0 * 16 + c0) * DIM)[lane];
    acc.x += t.x; acc.y += t.y; acc.z += t.z; acc.w += t.w;
    t = reinterpret_cast<const float4*>(bemb + (size_t)(1 * 16 + c1) * DIM)[lane];
    acc.x += t.x; acc.y += t.y; acc.z += t.z; acc.w += t.w;
    t = reinterpret_cast<const float4*>(bemb + (size_t)(2 * 16 + c2) * DIM)[lane];
    acc.x += t.x; acc.y += t.y; acc.z += t.z; acc.w += t.w;

    #pragma unroll
    for (int c = 0; c < NCB; ++c) {
        float ec = __shfl_sync(0xFFFFFFFFu, ev, c);
        float4 wv = reinterpret_cast<const float4*>(rbfW + (size_t)c * DIM)[lane];
        acc.x += ec * wv.x; acc.y += ec * wv.y; acc.z += ec * wv.z; acc.w += ec * wv.w;
    }
    reinterpret_cast<float4*>(bond_embed + (size_t)u * DIM)[lane] = acc;
}

// ---------------- block B scatter (linearized RBF): ----------------
// agg[dst] += bond_embed[src];  esum[dst][lane] += e_lane;  esum[dst][32] += 1
__global__ void k_scatter_b(const float* __restrict__ angle_float,
                            const int* __restrict__ src, const int* __restrict__ dst,
                            const float* __restrict__ bond_embed,
                            float* __restrict__ agg, float* __restrict__ esum) {
    int a = (blockIdx.x * blockDim.x + threadIdx.x) >> 5;
    int lane = threadIdx.x & 31;
    if (a >= NANG) return;
    float x = __ldg(&angle_float[a]);
    float dlt = x - 0.1f * (float)lane;
    float ev = __expf(-GAMMA * dlt * dlt);
    int s = __ldg(&src[a]);
    int d = __ldg(&dst[a]);
    float4 be = reinterpret_cast<const float4*>(bond_embed + (size_t)s * DIM)[lane];
    red_add_v4(agg + (size_t)d * DIM + lane * 4, be);
    red_add_f32(esum + (size_t)d * 36 + lane, ev);
    if (lane == 0) red_add_f32(esum + (size_t)d * 36 + 32, 1.f);
}

// ---------------- apply summed RBF: agg[u] += esum[u][0:32]@W + esum[u][32]*b --
__global__ void k_apply_rbf(const float* __restrict__ esum,
                            const float* __restrict__ rbfW,
                            const float* __restrict__ rbfb,
                            float* __restrict__ agg) {
    int u = (blockIdx.x * blockDim.x + threadIdx.x) >> 5;
    int lane = threadIdx.x & 31;
    if (u >= NB) return;
    float e = __ldg(&esum[(size_t)u * 36 + lane]);
    float cnt = __ldg(&esum[(size_t)u * 36 + 32]);
    float4 acc = make_float4(0.f, 0.f, 0.f, 0.f);
    #pragma unroll
    for (int c = 0; c < NCA; ++c) {
        float ec = __shfl_sync(0xFFFFFFFFu, e, c);
        float4 wv = reinterpret_cast<const float4*>(rbfW + (size_t)c * DIM)[lane];
        acc.x += ec * wv.x; acc.y += ec * wv.y; acc.z += ec * wv.z; acc.w += ec * wv.w;
    }
    float4 bv = reinterpret_cast<const float4*>(rbfb)[lane];
    acc.x += cnt * bv.x; acc.y += cnt * bv.y; acc.z += cnt * bv.z; acc.w += cnt * bv.w;
    float4* row = reinterpret_cast<float4*>(agg + (size_t)u * DIM);
    float4 cur = row[lane];
    cur.x += acc.x; cur.y += acc.y; cur.z += acc.z; cur.w += acc.w;
    row[lane] = cur;
}

// ---------------- fused tf32-MMA MLP + LN + graphnorm + relu + residual -------
// BM=32, 256 threads. Packed uint2 fragment layouts (one LDS.64 per fragment half).
// smem (uint2 units):
//   region1 [0, 4160): sAp [32][65] + sW1p [2][4][260]  (stage1)
//                      sHp [32][129]                    (stage2 A, overlaps)
//                      sC  fp32 [32][132]               (stage3, overlaps)
//   region2 [4160, 5216): sW2p [2][4][132]
#define RS_A   65
#define RS_H   129
#define W1_TG  260
#define W1_JL  1040
#define W2_TG  132
#define W2_JL  528
#define OFF_AP  0
#define OFF_W1P 2080
#define OFF_HP  0
#define OFF_W2P 4160
#define SMEM_U2 5216

template<int EDGE>
__global__ void __launch_bounds__(256, 3)
k_fused(const float* __restrict__ A,
        const float* __restrict__ w1, const float* __restrict__ b1,
        const float* __restrict__ w2, const float* __restrict__ b2,
        const float* __restrict__ lng, const float* __restrict__ lnb,
        const int* __restrict__ gid,
        const float* __restrict__ base,
        const float* __restrict__ bond_float, const int* __restrict__ bond_cat,
        const float* __restrict__ bemb,
        const float* __restrict__ rbfW, const float* __restrict__ rbfb,
        float* __restrict__ out, int M) {
    __shared__ uint2 smU2[SMEM_U2];
    float* smf = reinterpret_cast<float*>(smU2);

    const int tid  = threadIdx.x;
    const int lane = tid & 31;
    const int wrp  = tid >> 5;
    const int rowBase = blockIdx.x * 32;
    const int tig  = lane & 3;
    const int grp  = lane >> 2;

    // ---- load A tile packed: sAp[r][j*4+t] = (A[r][8j+t], A[r][8j+t+4]) ----
    #pragma unroll
    for (int i = 0; i < 8; ++i) {
        int flat = tid + i * 256;            // 0..2047
        int r = flat >> 6;
        int rem = flat & 63;
        int j = rem >> 2, t = rem & 3;
        const float* ap = A + (size_t)(rowBase + r) * DIM + 8 * j + t;
        smU2[OFF_AP + r * RS_A + j * 4 + t] = make_uint2(f2tf32(ap[0]), f2tf32(ap[4]));
    }

    // ---- stage 1: H[32][256] = relu(A @ W1 + b1) ----
    float d1[2][4][4];
    #pragma unroll
    for (int mt = 0; mt < 2; ++mt)
        #pragma unroll
        for (int nt = 0; nt < 4; ++nt)
            #pragma unroll
            for (int c = 0; c < 4; ++c) d1[mt][nt][c] = 0.f;

    for (int kc = 0; kc < 8; ++kc) {
        int kt = kc * 16;
        #pragma unroll
        for (int i = 0; i < 8; ++i) {
            int flat = tid + i * 256;        // 0..2047
            int pr = flat >> 8;              // 0..7
            int n = flat & 255;
            int jl = pr >> 2, tg = pr & 3;
            const float* wp = w1 + (size_t)(kt + 8 * jl + tg) * HID + n;
            smU2[OFF_W1P + jl * W1_JL + tg * W1_TG + n] =
                make_uint2(f2tf32(wp[0]), f2tf32(wp[4 * HID]));
        }
        __syncthreads();
        #pragma unroll
        for (int jg = 0; jg < 2; ++jg) {
            int j = kc * 2 + jg;
            uint2 pa[2][2];
            #pragma unroll
            for (int mt = 0; mt < 2; ++mt) {
                pa[mt][0] = smU2[OFF_AP + (grp + 16 * mt) * RS_A + j * 4 + tig];
                pa[mt][1] = smU2[OFF_AP + (grp + 8 + 16 * mt) * RS_A + j * 4 + tig];
            }
            #pragma unroll
            for (int nt = 0; nt < 4; ++nt) {
                int n = wrp * 32 + nt * 8 + grp;
                uint2 q = smU2[OFF_W1P + jg * W1_JL + tig * W1_TG + n];
                #pragma unroll
                for (int mt = 0; mt < 2; ++mt)
                    mma8(d1[mt][nt][0], d1[mt][nt][1], d1[mt][nt][2], d1[mt][nt][3],
                         pa[mt][0].x, pa[mt][1].x, pa[mt][0].y, pa[mt][1].y, q.x, q.y);
            }
        }
        __syncthreads();
    }

    // ---- H epilogue: bias+relu, pack into sHp (overlaps sAp/sW1p) ----
    #pragma unroll
    for (int nt = 0; nt < 4; ++nt) {
        int colbase = wrp * 32 + nt * 8;
        int j2 = colbase >> 3;
        #pragma unroll
        for (int dd = 0; dd < 2; ++dd) {
            int cc = 2 * tig + dd;           // 0..7
            int col = colbase + cc;
            int t2 = cc & 3, half = cc >> 2;
            float bb = b1[col];
            #pragma unroll
            for (int mt = 0; mt < 2; ++mt) {
                int r0 = grp + 16 * mt;
                float v0 = fmaxf(d1[mt][nt][dd] + bb, 0.f);
                float v1 = fmaxf(d1[mt][nt][2 + dd] + bb, 0.f);
                reinterpret_cast<unsigned*>(&smU2[OFF_HP + r0 * RS_H + j2 * 4 + t2])[half] = f2tf32(v0);
                reinterpret_cast<unsigned*>(&smU2[OFF_HP + (r0 + 8) * RS_H + j2 * 4 + t2])[half] = f2tf32(v1);
            }
        }
    }
    __syncthreads();

    // ---- stage 2: C[32][128] = H @ W2 + b2 ----
    float d2a[2][2][4];
    #pragma unroll
    for (int mt = 0; mt < 2; ++mt)
        #pragma unroll
        for (int nt = 0; nt < 2; ++nt)
            #pragma unroll
            for (int c = 0; c < 4; ++c) d2a[mt][nt][c] = 0.f;

    for (int kc = 0; kc < 16; ++kc) {
        int kt = kc * 16;
        #pragma unroll
        for (int i = 0; i < 4; ++i) {
            int flat = tid + i * 256;        // 0..1023
            int pr = flat >> 7;              // 0..7
            int n = flat & 127;
            int jl = pr >> 2, tg = pr & 3;
            const float* wp = w2 + (size_t)(kt + 8 * jl + tg) * DIM + n;
            smU2[OFF_W2P + jl * W2_JL + tg * W2_TG + n] =
                make_uint2(f2tf32(wp[0]), f2tf32(wp[4 * DIM]));
        }
        __syncthreads();
        #pragma unroll
        for (int jg = 0; jg < 2; ++jg) {
            int j = kc * 2 + jg;
            uint2 pa[2][2];
            #pragma unroll
            for (int mt = 0; mt < 2; ++mt) {
                pa[mt][0] = smU2[OFF_HP + (grp + 16 * mt) * RS_H + j * 4 + tig];
                pa[mt][1] = smU2[OFF_HP + (grp + 8 + 16 * mt) * RS_H + j * 4 + tig];
            }
            #pragma unroll
            for (int nt = 0; nt < 2; ++nt) {
                int n = wrp * 16 + nt * 8 + grp;
                uint2 q = smU2[OFF_W2P + jg * W2_JL + tig * W2_TG + n];
                #pragma unroll
                for (int mt = 0; mt < 2; ++mt)
                    mma8(d2a[mt][nt][0], d2a[mt][nt][1], d2a[mt][nt][2], d2a[mt][nt][3],
                         pa[mt][0].x, pa[mt][1].x, pa[mt][0].y, pa[mt][1].y, q.x, q.y);
            }
        }
        __syncthreads();
    }

    // ---- C epilogue: bias, fp32 into sC (overlaps sHp region) ----
    #pragma unroll
    for (int nt = 0; nt < 2; ++nt) {
        int col = wrp * 16 + nt * 8 + 2 * tig;
        float bb0 = b2[col], bb1 = b2[col + 1];
        #pragma unroll
        for (int mt = 0; mt < 2; ++mt) {
            int r0 = grp + 16 * mt;
            *reinterpret_cast<float2*>(&smf[r0 * 132 + col]) =
                make_float2(d2a[mt][nt][0] + bb0, d2a[mt][nt][1] + bb1);
            *reinterpret_cast<float2*>(&smf[(r0 + 8) * 132 + col]) =
                make_float2(d2a[mt][nt][2] + bb0, d2a[mt][nt][3] + bb1);
        }
    }
    __syncthreads();

    // ---- stage 3: per-row LN + sqrt-graphnorm + relu + residual ----
    #pragma unroll
    for (int rr = 0; rr < 4; ++rr) {
        int r = wrp + rr * 8;
        int u = rowBase + r;
        float4 v = *reinterpret_cast<const float4*>(&smf[r * 132 + lane * 4]);
        float mu = warp_sum(v.x + v.y + v.z + v.w) * (1.f / DIM);
        float4 dv = make_float4(v.x - mu, v.y - mu, v.z - mu, v.w - mu);
        float var = warp_sum(dv.x * dv.x + dv.y * dv.y + dv.z * dv.z + dv.w * dv.w) * (1.f / DIM);
        float rstd = rsqrtf(var + LN_EPS);
        int g = gid[u];
        float gn = rsqrtf(warp_seg_count(gid, M, u, g, lane));
        float4 gg = *reinterpret_cast<const float4*>(lng + lane * 4);
        float4 bb = *reinterpret_cast<const float4*>(lnb + lane * 4);
        float4 y;
        y.x = fmaxf((dv.x * rstd * gg.x + bb.x) * gn, 0.f);
        y.y = fmaxf((dv.y * rstd * gg.y + bb.y) * gn, 0.f);
        y.z = fmaxf((dv.z * rstd * gg.z + bb.z) * gn, 0.f);
        y.w = fmaxf((dv.w * rstd * gg.w + bb.w) * gn, 0.f);

        if (EDGE) {
            int e = 2 * u;
            float x = bond_float[e];
            float ev = 0.f;
            if (lane < NCB) {
                float dlt = x - 0.1f * (float)lane;
                ev = __expf(-GAMMA * dlt * dlt);
            }
            int c0 = bond_cat[(size_t)e * 3 + 0];
            int c1 = bond_cat[(size_t)e * 3 + 1];
            int c2 = bond_cat[(size_t)e * 3 + 2];
            float4 res = reinterpret_cast<const float4*>(rbfb)[lane];
            float4 t;
            t = reinterpret_cast<const float4*>(bemb + (size_t)(0 * 16 + c0) * DIM)[lane];
            res.x += t.x; res.y += t.y; res.z += t.z; res.w += t.w;
            t = reinterpret_cast<const float4*>(bemb + (size_t)(1 * 16 + c1) * DIM)[lane];
            res.x += t.x; res.y += t.y; res.z += t.z; res.w += t.w;
            t = reinterpret_cast<const float4*>(bemb + (size_t)(2 * 16 + c2) * DIM)[lane];
            res.x += t.x; res.y += t.y; res.z += t.z; res.w += t.w;
            #pragma unroll
            for (int c = 0; c < NCB; ++c) {
                float ec = __shfl_sync(0xFFFFFFFFu, ev, c);
                float4 wv = reinterpret_cast<const float4*>(rbfW + (size_t)c * DIM)[lane];
                res.x += ec * wv.x; res.y += ec * wv.y;
                res.z += ec * wv.z; res.w += ec * wv.w;
            }
            y.x += res.x; y.y += res.y; y.z += res.z; y.w += res.w;
            *reinterpret_cast<float4*>(out + (size_t)(2 * u) * DIM + lane * 4) = y;
            *reinterpret_cast<float4*>(out + (size_t)(2 * u + 1) * DIM + lane * 4) = y;
        } else {
            float4 res = reinterpret_cast<const float4*>(base + (size_t)u * DIM)[lane];
            y.x += res.x; y.y += res.y; y.z += res.z; y.w += res.w;
            *reinterpret_cast<float4*>(out + (size_t)u * DIM + lane * 4) = y;
        }
    }
}

// ---------------- launch ----------------
extern "C" void kernel_launch(void* const* d_in, const int* in_sizes, int n_in,
                              void* d_out, int out_size) {
    const float* node_feats  = (const float*)d_in[0];
    const float* edge_feats  = (const float*)d_in[1];
    const float* bond_float  = (const float*)d_in[2];
    const float* angle_float = (const float*)d_in[3];
    const float* bond_emb    = (const float*)d_in[4];
    const float* w1a = (const float*)d_in[5];
    const float* b1a = (const float*)d_in[6];
    const float* w2a = (const float*)d_in[7];
    const float* b2a = (const float*)d_in[8];
    const float* lng_a = (const float*)d_in[9];
    const float* lnb_a = (const float*)d_in[10];
    const float* w1b = (const float*)d_in[11];
    const float* b1b = (const float*)d_in[12];
    const float* w2b = (const float*)d_in[13];
    const float* b2b = (const float*)d_in[14];
    const float* lng_b = (const float*)d_in[15];
    const float* lnb_b = (const float*)d_in[16];
    const float* rbfb_W = (const float*)d_in[17];
    const float* rbfb_b = (const float*)d_in[18];
    const float* rbfa_W = (const float*)d_in[19];
    const float* rbfa_b = (const float*)d_in[20];
    const int* ab_src = (const int*)d_in[21];
    const int* ab_dst = (const int*)d_in[22];
    const int* ab_gid = (const int*)d_in[23];
    const int* ba_src = (const int*)d_in[24];
    const int* ba_dst = (const int*)d_in[25];
    const int* ba_gid = (const int*)d_in[26];
    const int* bond_cat = (const int*)d_in[27];

    float* outN = (float*)d_out;                        // NA*DIM
    float* outE = outN + (size_t)NA * DIM;              // NBD*DIM
    float* esum = outE + (size_t)NB * DIM;              // NB*36 scratch (edge rows [NB,..))

    const int N4 = NA * DIM / 4;

    // ---- Phase E (edge block) ----
    k_zero<<<2048, 256>>>(reinterpret_cast<float4*>(outN), N4);
    k_zero<<<512, 256>>>(reinterpret_cast<float4*>(esum), NB * 36 / 4);
    k_bond_embed<<<(NB * 32 + 255) / 256, 256>>>(bond_float, bond_cat, bond_emb,
                                                 rbfb_W, rbfb_b, outE);
    k_scatter_b<<<(NANG * 32 + 255) / 256, 256>>>(angle_float, ba_src, ba_dst,
                                                  outE, outN, esum);
    k_apply_rbf<<<(NB * 32 + 255) / 256, 256>>>(esum, rbfa_W, rbfa_b, outN);
    k_fused<1><<<NB / 32, 256>>>(outN, w1b, b1b, w2b, b2b, lng_b, lnb_b,
                                 ba_gid, nullptr,
                                 bond_float, bond_cat, bond_emb, rbfb_W, rbfb_b,
                                 outE, NB);

    // ---- Phase N (node block) ----
    k_zero<<<2048, 256>>>(reinterpret_cast<float4*>(outN), N4);
    k_scatter_a<<<(NBD * 32 + 255) / 256, 256>>>(node_feats, edge_feats, ab_src, ab_dst, outN);
    k_fused<0><<<NA / 32, 256>>>(outN, w1a, b1a, w2a, b2a, lng_a, lnb_a,
                                 ab_gid, node_feats,
                                 nullptr, nullptr, nullptr, nullptr, nullptr,
                                 outN, NA);
}